// round 11
// baseline (speedup 1.0000x reference)
#include <cuda_runtime.h>
#include <math.h>
#include <stdint.h>

// Problem constants
#define BB 2
#define CC 48
#define HH 64
#define WW 64
#define NN 4096
#define RPE_S 191
#define NSPLIT 4
#define KEYS_PER_SPLIT (NN / NSPLIT)

#define RP_ROWS 194
#define RP_STRIDE 196

// ---------------- scratch (device globals; no allocation allowed) -------------
__device__ float  g_q  [BB*CC*NN];
__device__ float  g_x2 [BB*96*NN];
__device__ float  g_pos[BB*NN*2];
__device__ float  g_xs [BB*CC*NN];
__device__ float  g_k  [BB*CC*NN];
__device__ float  g_v  [BB*CC*NN];
__device__ float  g_win[BB*CC*NN];
__device__ float  g_opart[NSPLIT*BB*CC*NN];
__device__ float  g_mpart[NSPLIT*BB*NN];
__device__ float  g_lpart[NSPLIT*BB*NN];
// quad-packed padded rpe: g_rpe4[r][xc] = (P[y][x], P[y+1][x], P[y][x+1], P[y+1][x+1])
__device__ float4 g_rpe4[RP_ROWS*RP_STRIDE];

// ---------------- tf32 MMA helpers ----------------------------------------------
__device__ __forceinline__ uint32_t f2tf(float f) {
    uint32_t r; asm("cvt.rna.tf32.f32 %0, %1;" : "=r"(r) : "f"(f)); return r;
}
__device__ __forceinline__ void mma_tf32(float* c,
                                         uint32_t a0, uint32_t a1, uint32_t a2, uint32_t a3,
                                         uint32_t b0, uint32_t b1) {
    asm("mma.sync.aligned.m16n8k8.row.col.f32.tf32.tf32.f32 "
        "{%0,%1,%2,%3}, {%4,%5,%6,%7}, {%8,%9}, {%0,%1,%2,%3};"
        : "+f"(c[0]), "+f"(c[1]), "+f"(c[2]), "+f"(c[3])
        : "r"(a0), "r"(a1), "r"(a2), "r"(a3), "r"(b0), "r"(b1));
}

// ---------------- shared 48x48 GEMM tile (128 pixels per block) -------------------
struct ConvSmem {
    float Xs[128 * 52];
    float Ws[48 * 64];
    float bias_s[48];
    float sc_s[48];
};

__device__ __forceinline__ void conv_fill(ConvSmem& S, const float* __restrict__ srcb,
                                          int m0, const float* __restrict__ W, int tid) {
    for (int i = tid; i < CC * 128; i += 256) {
        int c = i >> 7, m = i & 127;
        S.Xs[m * 52 + c] = __uint_as_float(f2tf(srcb[c * NN + m0 + m]));
    }
    for (int i = tid; i < 48 * 64; i += 256) {
        int c = i >> 6, o = i & 63;
        float v = (o < 48) ? W[o * CC + c] * S.sc_s[o] : 0.f;
        S.Ws[c * 64 + (o ^ ((c & 3) << 3))] = __uint_as_float(f2tf(v));
    }
}

__device__ __forceinline__ void conv_mma(const ConvSmem& S, float cS[6][4],
                                         int qrow, int tig, int gid) {
    const uint32_t* Xu = (const uint32_t*)S.Xs;
    const uint32_t* Wu = (const uint32_t*)S.Ws;
#pragma unroll
    for (int nb = 0; nb < 6; nb++) {
        int col = nb * 8 + 2 * tig;
        cS[nb][0] = cS[nb][2] = S.bias_s[col];
        cS[nb][1] = cS[nb][3] = S.bias_s[col + 1];
    }
    const int sw = tig << 3;
#pragma unroll
    for (int kb = 0; kb < 6; kb++) {
        uint32_t a0 = Xu[qrow * 52 + kb * 8 + tig];
        uint32_t a1 = Xu[(qrow + 8) * 52 + kb * 8 + tig];
        uint32_t a2 = Xu[qrow * 52 + kb * 8 + tig + 4];
        uint32_t a3 = Xu[(qrow + 8) * 52 + kb * 8 + tig + 4];
#pragma unroll
        for (int nb = 0; nb < 6; nb++) {
            uint32_t b0 = Wu[(kb * 8 + tig) * 64 + ((nb * 8 + gid) ^ sw)];
            uint32_t b1 = Wu[(kb * 8 + tig + 4) * 64 + ((nb * 8 + gid) ^ sw)];
            mma_tf32(cS[nb], a0, a1, a2, a3, b0, b1);
        }
    }
}

// ---------------- stage1: q + x2(BN) projections + rpe quad-pack -----------------
__global__ void __launch_bounds__(256, 2) stage1_kernel(
    const float* __restrict__ x,
    const float* __restrict__ Wq, const float* __restrict__ bq,
    const float* __restrict__ inp_w, const float* __restrict__ inp_b,
    const float* __restrict__ bng, const float* __restrict__ bnb,
    const float* __restrict__ bnm, const float* __restrict__ bnv,
    const float* __restrict__ rpe) {
    const int tid = threadIdx.x;
    if (blockIdx.y == 6) {
        for (int idx = blockIdx.x * 256 + tid; idx < RP_ROWS * RP_STRIDE; idx += 32 * 256) {
            int r  = idx / RP_STRIDE;
            int xc = idx - r * RP_STRIDE;
            int yy = r - 2, xx = xc - 2;
            float v00 = 0.f, v10 = 0.f, v01 = 0.f, v11 = 0.f;
            bool y0ok = (yy     >= 0 && yy     <= 190);
            bool y1ok = (yy + 1 >= 0 && yy + 1 <= 190);
            if (xx >= 0 && xx <= 190) {
                if (y0ok) v00 = rpe[yy * RPE_S + xx];
                if (y1ok) v10 = rpe[(yy + 1) * RPE_S + xx];
            }
            if (xx + 1 >= 0 && xx + 1 <= 190) {
                if (y0ok) v01 = rpe[yy * RPE_S + xx + 1];
                if (y1ok) v11 = rpe[(yy + 1) * RPE_S + xx + 1];
            }
            g_rpe4[idx] = make_float4(v00, v10, v01, v11);
        }
        return;
    }
    __shared__ ConvSmem S;
    const int job = blockIdx.y >> 1;
    const int b   = blockIdx.y & 1;
    const int m0  = blockIdx.x * 128;

    const float* W;
    const float* bi;
    const float* srcb = x + b * CC * NN;
    float* dstb;
    int bnoff = -1;
    if (job == 0)      { W = Wq;              bi = bq;          dstb = g_q  + b * CC * NN; }
    else if (job == 1) { W = inp_w;           bi = inp_b;       dstb = g_x2 + b * 96 * NN;            bnoff = 0;  }
    else               { W = inp_w + 48 * CC; bi = inp_b + 48;  dstb = g_x2 + (b * 96 + 48) * NN;     bnoff = 48; }

    if (tid < 48) {
        if (bnoff < 0) { S.sc_s[tid] = 1.f; S.bias_s[tid] = bi[tid]; }
        else {
            float sc = rsqrtf(bnv[bnoff + tid] + 1e-5f) * bng[bnoff + tid];
            S.sc_s[tid]   = sc;
            S.bias_s[tid] = (bi[tid] - bnm[bnoff + tid]) * sc + bnb[bnoff + tid];
        }
    }
    __syncthreads();
    conv_fill(S, srcb, m0, W, tid);
    __syncthreads();

    const int warp = tid >> 5, lane = tid & 31;
    const int gid = lane >> 2, tig = lane & 3;
    const int qrow = warp * 16 + gid;
    float cS[6][4];
    conv_mma(S, cS, qrow, tig, gid);

#pragma unroll
    for (int nb = 0; nb < 6; nb++) {
        int col = nb * 8 + 2 * tig;
        dstb[col * NN + m0 + qrow]           = cS[nb][0];
        dstb[(col + 1) * NN + m0 + qrow]     = cS[nb][1];
        dstb[col * NN + m0 + qrow + 8]       = cS[nb][2];
        dstb[(col + 1) * NN + m0 + qrow + 8] = cS[nb][3];
    }
}

// ---------------- stage2: k,v projections -----------------------------------------
__global__ void __launch_bounds__(256, 2) stage2_kernel(
    const float* __restrict__ Wk, const float* __restrict__ bk,
    const float* __restrict__ Wv, const float* __restrict__ bv) {
    __shared__ ConvSmem S;
    const int tid = threadIdx.x;
    const int job = blockIdx.y >> 1;
    const int b   = blockIdx.y & 1;
    const int m0  = blockIdx.x * 128;
    const float* W  = job ? Wv : Wk;
    const float* bi = job ? bv : bk;
    float* dstb = (job ? g_v : g_k) + b * CC * NN;
    const float* srcb = g_xs + b * CC * NN;

    if (tid < 48) { S.sc_s[tid] = 1.f; S.bias_s[tid] = bi[tid]; }
    __syncthreads();
    conv_fill(S, srcb, m0, W, tid);
    __syncthreads();

    const int warp = tid >> 5, lane = tid & 31;
    const int gid = lane >> 2, tig = lane & 3;
    const int qrow = warp * 16 + gid;
    float cS[6][4];
    conv_mma(S, cS, qrow, tig, gid);

#pragma unroll
    for (int nb = 0; nb < 6; nb++) {
        int col = nb * 8 + 2 * tig;
        dstb[col * NN + m0 + qrow]           = cS[nb][0];
        dstb[(col + 1) * NN + m0 + qrow]     = cS[nb][1];
        dstb[col * NN + m0 + qrow + 8]       = cS[nb][2];
        dstb[(col + 1) * NN + m0 + qrow + 8] = cS[nb][3];
    }
}

// ---------------- offset head + position + grid-sample x (512 thr) --------------
__global__ void deform_kernel(const float* __restrict__ x,
                              const float* __restrict__ dww, const float* __restrict__ dwb,
                              const float* __restrict__ lng, const float* __restrict__ lnb,
                              const float* __restrict__ pww) {
    int b = blockIdx.y;
    int y = blockIdx.x;
    int tid = threadIdx.x;
    __shared__ float ts[CC * WW];
    __shared__ float posr[WW * 2];
    __shared__ float redA[8][WW];
    __shared__ float redB[8][WW];

    for (int i = tid; i < CC * WW; i += 512) {
        int c = i >> 6, px = i & 63;
        float acc = dwb[c];
        const float* qc = g_q + (b * CC + c) * NN;
        const float* wc = dww + c * 9;
#pragma unroll
        for (int ky = 0; ky < 3; ky++) {
            int yy = y + ky - 1;
            if (yy < 0 || yy > 63) continue;
#pragma unroll
            for (int kx = 0; kx < 3; kx++) {
                int xx = px + kx - 1;
                if (xx < 0 || xx > 63) continue;
                acc += qc[(yy << 6) + xx] * wc[ky * 3 + kx];
            }
        }
        ts[c * 64 + px] = acc;
    }
    __syncthreads();

    const int sub = tid >> 6;
    const int px  = tid & 63;
    {
        float s = 0.f;
#pragma unroll
        for (int j = 0; j < 6; j++) s += ts[(sub * 6 + j) * 64 + px];
        redA[sub][px] = s;
    }
    __syncthreads();
    float mu = 0.f;
#pragma unroll
    for (int u = 0; u < 8; u++) mu += redA[u][px];
    mu *= (1.f / 48.f);
    {
        float v2 = 0.f;
#pragma unroll
        for (int j = 0; j < 6; j++) {
            float d = ts[(sub * 6 + j) * 64 + px] - mu;
            v2 += d * d;
        }
        redB[sub][px] = v2;
    }
    __syncthreads();
    float var = 0.f;
#pragma unroll
    for (int u = 0; u < 8; u++) var += redB[u][px];
    float rs = rsqrtf(var * (1.f / 48.f) + 1e-5f);
    {
        float a0 = 0.f, a1 = 0.f;
#pragma unroll
        for (int j = 0; j < 6; j++) {
            int c = sub * 6 + j;
            float v = (ts[c * 64 + px] - mu) * rs * lng[c] + lnb[c];
            v = 0.5f * v * (1.f + erff(v * 0.7071067811865475f));
            a0 += pww[c] * v;
            a1 += pww[CC + c] * v;
        }
        redA[sub][px] = a0;
        redB[sub][px] = a1;
    }
    __syncthreads();
    if (tid < WW) {
        float a0 = 0.f, a1 = 0.f;
#pragma unroll
        for (int u = 0; u < 8; u++) { a0 += redA[u][px]; a1 += redB[u][px]; }
        float py  = tanhf(a0) * (2.f / 63.f) + ((0.5f + (float)y ) * (2.f / 63.f) - 1.f);
        float pxx = tanhf(a1) * (2.f / 63.f) + ((0.5f + (float)px) * (2.f / 63.f) - 1.f);
        posr[px * 2 + 0] = py;
        posr[px * 2 + 1] = pxx;
        int n = (y << 6) + px;
        g_pos[(b * NN + n) * 2 + 0] = py;
        g_pos[(b * NN + n) * 2 + 1] = pxx;
    }
    __syncthreads();

    for (int i = tid; i < CC * WW; i += 512) {
        int c = i >> 6, p = i & 63;
        float py  = posr[p * 2 + 0];
        float pxx = posr[p * 2 + 1];
        float gx = (pxx + 1.f) * 0.5f * 63.f;
        float gy = (py  + 1.f) * 0.5f * 63.f;
        const float* img = x + (b * CC + c) * NN;
        float x0f = floorf(gx), y0f = floorf(gy);
        int   x0 = (int)x0f, y0 = (int)y0f;
        float wx = gx - x0f, wy = gy - y0f;
        float acc = 0.f;
#pragma unroll
        for (int dy = 0; dy < 2; dy++) {
            int yc = y0 + dy;
            if (yc < 0 || yc >= HH) continue;
            float wyv = dy ? wy : (1.f - wy);
#pragma unroll
            for (int dx = 0; dx < 2; dx++) {
                int xc = x0 + dx;
                if (xc < 0 || xc >= WW) continue;
                float wxv = dx ? wx : (1.f - wx);
                acc += img[yc * WW + xc] * (wyv * wxv);
            }
        }
        g_xs[(b * CC + c) * NN + (y << 6) + p] = acc;
    }
}

// ---------------- fused flash attention: 64 queries / 128 threads / 4 CTAs/SM ----
// block = one image row (64 queries), 4 warps; warp owns 16-query strip.
// smem: Qs 64x52, Ks 48x64 swizzled, Vs 64x56, Ps 64x66 -> 56832 B -> 4 CTAs/SM.
#define AOF_QS 0
#define AOF_KS (AOF_QS + 64*52)
#define AOF_VS (AOF_KS + 48*64)
#define AOF_PS (AOF_VS + 64*56)
#define ATTN_SMEM_FLOATS (AOF_PS + 64*66)
#define ATTN_SMEM_BYTES (ATTN_SMEM_FLOATS * 4)

__global__ void __launch_bounds__(128, 4) attn_kernel() {
    extern __shared__ float sm[];
    float* Qs = sm + AOF_QS;
    float* Ks = sm + AOF_KS;
    float* Vs = sm + AOF_VS;
    float* Ps = sm + AOF_PS;
    const uint32_t* Qu = (const uint32_t*)Qs;
    const uint32_t* Ku = (const uint32_t*)Ks;
    const uint32_t* Vu = (const uint32_t*)Vs;
    const uint32_t* Pu = (const uint32_t*)Ps;

    const int y     = blockIdx.x;       // image row = 64 queries
    const int split = blockIdx.y;
    const int b     = blockIdx.z;
    const int tid   = threadIdx.x;
    const int warp  = tid >> 5;         // 0..3
    const int lane  = tid & 31;
    const int gid   = lane >> 2;
    const int tig   = lane & 3;
    const int m0    = y * 64;
    const int qrow  = warp * 16 + gid;  // 0..63 (with +8)

    const float scale = 0.14433756729740643f;
    const float step  = 95.0f / 63.0f;
    const float gyq   = 47.5f + (float)y * step;

    // load Q tile [m][c] (stride 52), scaled, tf32
    for (int i = tid; i < CC * 64; i += 128) {
        int c = i >> 6, m = i & 63;
        Qs[m * 52 + c] = __uint_as_float(f2tf(g_q[(b * CC + c) * NN + m0 + m] * scale));
    }

    float rmax0 = -1e30f, rmax1 = -1e30f, rsum0 = 0.f, rsum1 = 0.f;
    float o[6][4];
#pragma unroll
    for (int nb = 0; nb < 6; nb++)
#pragma unroll
        for (int j = 0; j < 4; j++) o[nb][j] = 0.f;

    const int nbase = split * KEYS_PER_SPLIT;
    for (int t = 0; t < KEYS_PER_SPLIT / 64; t++) {
        const int n0 = nbase + t * 64;
        __syncthreads();

        // K tile swizzled
        for (int i = tid; i < CC * 64; i += 128) {
            int c = i >> 6, n = i & 63;
            Ks[c * 64 + (n ^ ((c & 3) << 3))] =
                __uint_as_float(f2tf(g_k[(b * CC + c) * NN + n0 + n]));
        }

        // bias -> Ps[m][n] (stride 66): warp owns 16 keys; qy constant per block
#pragma unroll
        for (int kk = 0; kk < 16; kk++) {
            int n = warp * 16 + kk;
            float py = g_pos[(b * NN + n0 + n) * 2 + 0];
            float px = g_pos[(b * NN + n0 + n) * 2 + 1];
            float kbx = 47.5f * px;
            float gy = gyq - 47.5f * py;
            float yf = floorf(gy);
            int   iy = (int)yf;
            float fy = gy - yf;
            iy = min(max(iy, -2), 191);
            const float4* row = g_rpe4 + (iy + 2) * RP_STRIDE;
#pragma unroll
            for (int it = 0; it < 2; it++) {
                int m = it * 32 + lane;
                float gx = 47.5f + (float)m * step - kbx;
                float xf = floorf(gx);
                float fx = gx - xf;
                int   xi = (int)xf;
                xi = min(max(xi, -2), 192);
                float4 q4 = row[xi + 2];
                float b0 = fmaf(fx, q4.z - q4.x, q4.x);
                float b1 = fmaf(fx, q4.w - q4.y, q4.y);
                Ps[m * 66 + n] = fmaf(fy, b1 - b0, b0);
            }
        }
        __syncthreads();

        // V tile [n][56]
        for (int i = tid; i < CC * 64; i += 128) {
            int c = i >> 6, n = i & 63;
            Vs[n * 56 + c] = __uint_as_float(f2tf(g_v[(b * CC + c) * NN + n0 + n]));
        }

        // ---- S = QK^T + bias ----
        float cS[8][4];
#pragma unroll
        for (int nb = 0; nb < 8; nb++) {
            int col = nb * 8 + 2 * tig;
            float2 bA = *(const float2*)&Ps[qrow * 66 + col];
            float2 bB = *(const float2*)&Ps[(qrow + 8) * 66 + col];
            cS[nb][0] = bA.x; cS[nb][1] = bA.y;
            cS[nb][2] = bB.x; cS[nb][3] = bB.y;
        }
#pragma unroll
        for (int kb = 0; kb < 6; kb++) {
            uint32_t a0 = Qu[qrow * 52 + kb * 8 + tig];
            uint32_t a1 = Qu[(qrow + 8) * 52 + kb * 8 + tig];
            uint32_t a2 = Qu[qrow * 52 + kb * 8 + tig + 4];
            uint32_t a3 = Qu[(qrow + 8) * 52 + kb * 8 + tig + 4];
            const int sw = tig << 3;
#pragma unroll
            for (int nb = 0; nb < 8; nb++) {
                uint32_t b0 = Ku[(kb * 8 + tig) * 64 + ((nb * 8 + gid) ^ sw)];
                uint32_t b1 = Ku[(kb * 8 + tig + 4) * 64 + ((nb * 8 + gid) ^ sw)];
                mma_tf32(cS[nb], a0, a1, a2, a3, b0, b1);
            }
        }

        // ---- online softmax ----
        float tmax0 = -1e30f, tmax1 = -1e30f;
#pragma unroll
        for (int nb = 0; nb < 8; nb++) {
            tmax0 = fmaxf(tmax0, fmaxf(cS[nb][0], cS[nb][1]));
            tmax1 = fmaxf(tmax1, fmaxf(cS[nb][2], cS[nb][3]));
        }
        tmax0 = fmaxf(tmax0, __shfl_xor_sync(0xffffffffu, tmax0, 1));
        tmax0 = fmaxf(tmax0, __shfl_xor_sync(0xffffffffu, tmax0, 2));
        tmax1 = fmaxf(tmax1, __shfl_xor_sync(0xffffffffu, tmax1, 1));
        tmax1 = fmaxf(tmax1, __shfl_xor_sync(0xffffffffu, tmax1, 2));
        float nmax0 = fmaxf(rmax0, tmax0);
        float nmax1 = fmaxf(rmax1, tmax1);
        float f0 = __expf(rmax0 - nmax0);
        float f1 = __expf(rmax1 - nmax1);
        rmax0 = nmax0; rmax1 = nmax1;

        float psum0 = 0.f, psum1 = 0.f;
#pragma unroll
        for (int nb = 0; nb < 8; nb++) {
            float p0 = __expf(cS[nb][0] - nmax0);
            float p1 = __expf(cS[nb][1] - nmax0);
            float p2 = __expf(cS[nb][2] - nmax1);
            float p3 = __expf(cS[nb][3] - nmax1);
            psum0 += p0 + p1;
            psum1 += p2 + p3;
            int col = nb * 8 + 2 * tig;
            float2 w0 = make_float2(__uint_as_float(f2tf(p0)), __uint_as_float(f2tf(p1)));
            float2 w1 = make_float2(__uint_as_float(f2tf(p2)), __uint_as_float(f2tf(p3)));
            *(float2*)&Ps[qrow * 66 + col]       = w0;
            *(float2*)&Ps[(qrow + 8) * 66 + col] = w1;
        }
        psum0 += __shfl_xor_sync(0xffffffffu, psum0, 1);
        psum0 += __shfl_xor_sync(0xffffffffu, psum0, 2);
        psum1 += __shfl_xor_sync(0xffffffffu, psum1, 1);
        psum1 += __shfl_xor_sync(0xffffffffu, psum1, 2);
        rsum0 = rsum0 * f0 + psum0;
        rsum1 = rsum1 * f1 + psum1;

#pragma unroll
        for (int nb = 0; nb < 6; nb++) {
            o[nb][0] *= f0; o[nb][1] *= f0;
            o[nb][2] *= f1; o[nb][3] *= f1;
        }
        __syncthreads();

        // ---- PV: O += P x V ----
#pragma unroll
        for (int kb = 0; kb < 8; kb++) {
            uint32_t a0 = Pu[qrow * 66 + kb * 8 + tig];
            uint32_t a1 = Pu[(qrow + 8) * 66 + kb * 8 + tig];
            uint32_t a2 = Pu[qrow * 66 + kb * 8 + tig + 4];
            uint32_t a3 = Pu[(qrow + 8) * 66 + kb * 8 + tig + 4];
#pragma unroll
            for (int nb = 0; nb < 6; nb++) {
                uint32_t b0 = Vu[(kb * 8 + tig) * 56 + nb * 8 + gid];
                uint32_t b1 = Vu[(kb * 8 + tig + 4) * 56 + nb * 8 + gid];
                mma_tf32(o[nb], a0, a1, a2, a3, b0, b1);
            }
        }
    }

    const int mA = m0 + qrow;
    const int mB = mA + 8;
    float* op = g_opart + (split * BB + b) * CC * NN;
#pragma unroll
    for (int nb = 0; nb < 6; nb++) {
        int ch = nb * 8 + 2 * tig;
        op[ch * NN + mA]       = o[nb][0];
        op[(ch + 1) * NN + mA] = o[nb][1];
        op[ch * NN + mB]       = o[nb][2];
        op[(ch + 1) * NN + mB] = o[nb][3];
    }
    if (tig == 0) {
        g_mpart[(split * BB + b) * NN + mA] = rmax0;
        g_mpart[(split * BB + b) * NN + mB] = rmax1;
        g_lpart[(split * BB + b) * NN + mA] = rsum0;
        g_lpart[(split * BB + b) * NN + mB] = rsum1;
    }
}

// ---------------- window attention: 4 windows per 256-thread block --------------
__global__ void __launch_bounds__(256, 4) winattn_kernel() {
    int b  = blockIdx.z;
    int sp = blockIdx.y;
    int wg = threadIdx.x >> 6;
    int w  = blockIdx.x * 4 + wg;
    int t  = threadIdx.x & 63;

    __shared__ float qsm[4][64][17];
    __shared__ float vsm[4][64][17];

    int py, px;
    if (sp == 0)      { int wy = w >> 3, wx = w & 7; py = wy * 8 + (t >> 3); px = wx * 8 + (t & 7); }
    else if (sp == 1) { py = t;  px = w; }
    else              { py = w;  px = t; }
    int pix = py * 64 + px;

    int qbase = (b * 96 + sp * 32) * NN + pix;
#pragma unroll
    for (int c = 0; c < 16; c++) {
        qsm[wg][t][c] = g_x2[qbase + c * NN];
        vsm[wg][t][c] = g_x2[qbase + (16 + c) * NN];
    }
    __syncthreads();

    float qr[16];
#pragma unroll
    for (int c = 0; c < 16; c++) qr[c] = qsm[wg][t][c];

    float lg[64];
    float mx = -1e30f;
    for (int j = 0; j < 64; j++) {
        float d = 0.f;
#pragma unroll
        for (int c = 0; c < 16; c++) d += qr[c] * qsm[wg][j][c];
        lg[j] = d;
        mx = fmaxf(mx, d);
    }
    float s = 0.f;
    for (int j = 0; j < 64; j++) { lg[j] = __expf(lg[j] - mx); s += lg[j]; }
    float inv = 1.f / s;

    float o[16];
#pragma unroll
    for (int c = 0; c < 16; c++) o[c] = 0.f;
    for (int j = 0; j < 64; j++) {
        float p = lg[j] * inv;
#pragma unroll
        for (int c = 0; c < 16; c++) o[c] += p * vsm[wg][j][c];
    }
#pragma unroll
    for (int c = 0; c < 16; c++)
        g_win[(b * CC + sp * 16 + c) * NN + pix] = o[c];
}

// ---------------- final: MMA pout conv + split merge + average -------------------
__global__ void __launch_bounds__(256, 2) final_kernel(
    const float* __restrict__ pw, const float* __restrict__ pb,
    float* __restrict__ out) {
    __shared__ ConvSmem S;
    const int tid = threadIdx.x;
    const int b   = blockIdx.y;
    const int m0  = blockIdx.x * 128;

    if (tid < 48) { S.sc_s[tid] = 1.f; S.bias_s[tid] = pb[tid]; }
    __syncthreads();
    conv_fill(S, g_win + b * CC * NN, m0, pw, tid);
    __syncthreads();

    const int warp = tid >> 5, lane = tid & 31;
    const int gid = lane >> 2, tig = lane & 3;
    const int qrow = warp * 16 + gid;
    float cS[6][4];
    conv_mma(S, cS, qrow, tig, gid);

    const int mA = m0 + qrow;
    const int mB = mA + 8;

    float eA[NSPLIT], eB[NSPLIT];
    {
        float MA = -1e30f, MB = -1e30f;
        float mvA[NSPLIT], mvB[NSPLIT];
#pragma unroll
        for (int s = 0; s < NSPLIT; s++) {
            mvA[s] = g_mpart[(s * BB + b) * NN + mA];
            mvB[s] = g_mpart[(s * BB + b) * NN + mB];
            MA = fmaxf(MA, mvA[s]); MB = fmaxf(MB, mvB[s]);
        }
        float lA = 0.f, lB = 0.f;
#pragma unroll
        for (int s = 0; s < NSPLIT; s++) {
            eA[s] = __expf(mvA[s] - MA);
            eB[s] = __expf(mvB[s] - MB);
            lA += g_lpart[(s * BB + b) * NN + mA] * eA[s];
            lB += g_lpart[(s * BB + b) * NN + mB] * eB[s];
        }
        float ilA = 0.5f / lA, ilB = 0.5f / lB;
#pragma unroll
        for (int s = 0; s < NSPLIT; s++) { eA[s] *= ilA; eB[s] *= ilB; }
    }

#pragma unroll
    for (int nb = 0; nb < 6; nb++) {
        int col = nb * 8 + 2 * tig;
#pragma unroll
        for (int j = 0; j < 2; j++) {
            int ch = col + j;
            float odA = 0.f, odB = 0.f;
#pragma unroll
            for (int s = 0; s < NSPLIT; s++) {
                odA += g_opart[((s * BB + b) * CC + ch) * NN + mA] * eA[s];
                odB += g_opart[((s * BB + b) * CC + ch) * NN + mB] * eB[s];
            }
            out[(b * CC + ch) * NN + mA] = 0.5f * cS[nb][j]     + odA;
            out[(b * CC + ch) * NN + mB] = 0.5f * cS[nb][2 + j] + odB;
        }
    }
}

// ---------------- launch ---------------------------------------------------------
extern "C" void kernel_launch(void* const* d_in, const int* in_sizes, int n_in,
                              void* d_out, int out_size) {
    const float* x        = (const float*)d_in[0];
    const float* Wq       = (const float*)d_in[1];
    const float* bq       = (const float*)d_in[2];
    const float* off_dw_w = (const float*)d_in[3];
    const float* off_dw_b = (const float*)d_in[4];
    const float* off_ln_g = (const float*)d_in[5];
    const float* off_ln_b = (const float*)d_in[6];
    const float* off_pw_w = (const float*)d_in[7];
    const float* Wk       = (const float*)d_in[8];
    const float* bk       = (const float*)d_in[9];
    const float* Wv       = (const float*)d_in[10];
    const float* bv       = (const float*)d_in[11];
    const float* inp_w    = (const float*)d_in[12];
    const float* inp_b    = (const float*)d_in[13];
    const float* bn_g     = (const float*)d_in[14];
    const float* bn_b     = (const float*)d_in[15];
    const float* bn_mean  = (const float*)d_in[16];
    const float* bn_var   = (const float*)d_in[17];
    const float* pout_w   = (const float*)d_in[18];
    const float* pout_b   = (const float*)d_in[19];
    const float* rpe      = (const float*)d_in[20];
    float* out = (float*)d_out;

    cudaFuncSetAttribute(attn_kernel, cudaFuncAttributeMaxDynamicSharedMemorySize,
                         ATTN_SMEM_BYTES);

    stage1_kernel<<<dim3(32, 7), 256>>>(x, Wq, bq, inp_w, inp_b,
                                        bn_g, bn_b, bn_mean, bn_var, rpe);
    deform_kernel<<<dim3(HH, BB), 512>>>(x, off_dw_w, off_dw_b,
                                         off_ln_g, off_ln_b, off_pw_w);
    stage2_kernel<<<dim3(32, 4), 256>>>(Wk, bk, Wv, bv);
    attn_kernel<<<dim3(HH, NSPLIT, BB), 128, ATTN_SMEM_BYTES>>>();
    winattn_kernel<<<dim3(16, 3, BB), 256>>>();
    final_kernel<<<dim3(32, BB), 256>>>(pout_w, pout_b, out);
}

// round 12
// speedup vs baseline: 1.0004x; 1.0004x over previous
#include <cuda_runtime.h>
#include <math.h>
#include <stdint.h>

// Problem constants
#define BB 2
#define CC 48
#define HH 64
#define WW 64
#define NN 4096
#define RPE_S 191
#define NSPLIT 4
#define KEYS_PER_SPLIT (NN / NSPLIT)

#define RP_ROWS 194
#define RP_STRIDE 196

// ---------------- scratch (device globals; no allocation allowed) -------------
__device__ float  g_q  [BB*CC*NN];
__device__ float  g_x2 [BB*96*NN];
__device__ float  g_pos[BB*NN*2];
__device__ float  g_xs [BB*CC*NN];
__device__ float  g_k  [BB*CC*NN];
__device__ float  g_v  [BB*CC*NN];
__device__ float  g_win[BB*CC*NN];
__device__ float  g_opart[NSPLIT*BB*CC*NN];
__device__ float  g_mpart[NSPLIT*BB*NN];
__device__ float  g_lpart[NSPLIT*BB*NN];
__device__ float4 g_rpe4[RP_ROWS*RP_STRIDE];
__device__ float  g_bias[BB*NN*NN];      // [b][key n][query m]  (134 MB)

// ---------------- tf32 MMA helpers ----------------------------------------------
__device__ __forceinline__ uint32_t f2tf(float f) {
    uint32_t r; asm("cvt.rna.tf32.f32 %0, %1;" : "=r"(r) : "f"(f)); return r;
}
__device__ __forceinline__ void mma_tf32(float* c,
                                         uint32_t a0, uint32_t a1, uint32_t a2, uint32_t a3,
                                         uint32_t b0, uint32_t b1) {
    asm("mma.sync.aligned.m16n8k8.row.col.f32.tf32.tf32.f32 "
        "{%0,%1,%2,%3}, {%4,%5,%6,%7}, {%8,%9}, {%0,%1,%2,%3};"
        : "+f"(c[0]), "+f"(c[1]), "+f"(c[2]), "+f"(c[3])
        : "r"(a0), "r"(a1), "r"(a2), "r"(a3), "r"(b0), "r"(b1));
}

// ---------------- shared 48x48 GEMM tile (128 pixels per block) -------------------
struct ConvSmem {
    float Xs[128 * 52];
    float Ws[48 * 64];
    float bias_s[48];
    float sc_s[48];
};

__device__ __forceinline__ void conv_fill(ConvSmem& S, const float* __restrict__ srcb,
                                          int m0, const float* __restrict__ W, int tid) {
    for (int i = tid; i < CC * 128; i += 256) {
        int c = i >> 7, m = i & 127;
        S.Xs[m * 52 + c] = __uint_as_float(f2tf(srcb[c * NN + m0 + m]));
    }
    for (int i = tid; i < 48 * 64; i += 256) {
        int c = i >> 6, o = i & 63;
        float v = (o < 48) ? W[o * CC + c] * S.sc_s[o] : 0.f;
        S.Ws[c * 64 + (o ^ ((c & 3) << 3))] = __uint_as_float(f2tf(v));
    }
}

__device__ __forceinline__ void conv_mma(const ConvSmem& S, float cS[6][4],
                                         int qrow, int tig, int gid) {
    const uint32_t* Xu = (const uint32_t*)S.Xs;
    const uint32_t* Wu = (const uint32_t*)S.Ws;
#pragma unroll
    for (int nb = 0; nb < 6; nb++) {
        int col = nb * 8 + 2 * tig;
        cS[nb][0] = cS[nb][2] = S.bias_s[col];
        cS[nb][1] = cS[nb][3] = S.bias_s[col + 1];
    }
    const int sw = tig << 3;
#pragma unroll
    for (int kb = 0; kb < 6; kb++) {
        uint32_t a0 = Xu[qrow * 52 + kb * 8 + tig];
        uint32_t a1 = Xu[(qrow + 8) * 52 + kb * 8 + tig];
        uint32_t a2 = Xu[qrow * 52 + kb * 8 + tig + 4];
        uint32_t a3 = Xu[(qrow + 8) * 52 + kb * 8 + tig + 4];
#pragma unroll
        for (int nb = 0; nb < 6; nb++) {
            uint32_t b0 = Wu[(kb * 8 + tig) * 64 + ((nb * 8 + gid) ^ sw)];
            uint32_t b1 = Wu[(kb * 8 + tig + 4) * 64 + ((nb * 8 + gid) ^ sw)];
            mma_tf32(cS[nb], a0, a1, a2, a3, b0, b1);
        }
    }
}

// ---------------- stage1: q + x2(BN) projections + rpe quad-pack -----------------
__global__ void __launch_bounds__(256, 2) stage1_kernel(
    const float* __restrict__ x,
    const float* __restrict__ Wq, const float* __restrict__ bq,
    const float* __restrict__ inp_w, const float* __restrict__ inp_b,
    const float* __restrict__ bng, const float* __restrict__ bnb,
    const float* __restrict__ bnm, const float* __restrict__ bnv,
    const float* __restrict__ rpe) {
    const int tid = threadIdx.x;
    if (blockIdx.y == 6) {
        for (int idx = blockIdx.x * 256 + tid; idx < RP_ROWS * RP_STRIDE; idx += 32 * 256) {
            int r  = idx / RP_STRIDE;
            int xc = idx - r * RP_STRIDE;
            int yy = r - 2, xx = xc - 2;
            float v00 = 0.f, v10 = 0.f, v01 = 0.f, v11 = 0.f;
            bool y0ok = (yy     >= 0 && yy     <= 190);
            bool y1ok = (yy + 1 >= 0 && yy + 1 <= 190);
            if (xx >= 0 && xx <= 190) {
                if (y0ok) v00 = rpe[yy * RPE_S + xx];
                if (y1ok) v10 = rpe[(yy + 1) * RPE_S + xx];
            }
            if (xx + 1 >= 0 && xx + 1 <= 190) {
                if (y0ok) v01 = rpe[yy * RPE_S + xx + 1];
                if (y1ok) v11 = rpe[(yy + 1) * RPE_S + xx + 1];
            }
            g_rpe4[idx] = make_float4(v00, v10, v01, v11);
        }
        return;
    }
    __shared__ ConvSmem S;
    const int job = blockIdx.y >> 1;
    const int b   = blockIdx.y & 1;
    const int m0  = blockIdx.x * 128;

    const float* W;
    const float* bi;
    const float* srcb = x + b * CC * NN;
    float* dstb;
    int bnoff = -1;
    if (job == 0)      { W = Wq;              bi = bq;          dstb = g_q  + b * CC * NN; }
    else if (job == 1) { W = inp_w;           bi = inp_b;       dstb = g_x2 + b * 96 * NN;            bnoff = 0;  }
    else               { W = inp_w + 48 * CC; bi = inp_b + 48;  dstb = g_x2 + (b * 96 + 48) * NN;     bnoff = 48; }

    if (tid < 48) {
        if (bnoff < 0) { S.sc_s[tid] = 1.f; S.bias_s[tid] = bi[tid]; }
        else {
            float sc = rsqrtf(bnv[bnoff + tid] + 1e-5f) * bng[bnoff + tid];
            S.sc_s[tid]   = sc;
            S.bias_s[tid] = (bi[tid] - bnm[bnoff + tid]) * sc + bnb[bnoff + tid];
        }
    }
    __syncthreads();
    conv_fill(S, srcb, m0, W, tid);
    __syncthreads();

    const int warp = tid >> 5, lane = tid & 31;
    const int gid = lane >> 2, tig = lane & 3;
    const int qrow = warp * 16 + gid;
    float cS[6][4];
    conv_mma(S, cS, qrow, tig, gid);

#pragma unroll
    for (int nb = 0; nb < 6; nb++) {
        int col = nb * 8 + 2 * tig;
        dstb[col * NN + m0 + qrow]           = cS[nb][0];
        dstb[(col + 1) * NN + m0 + qrow]     = cS[nb][1];
        dstb[col * NN + m0 + qrow + 8]       = cS[nb][2];
        dstb[(col + 1) * NN + m0 + qrow + 8] = cS[nb][3];
    }
}

// ---------------- stage2: k,v projections -----------------------------------------
__global__ void __launch_bounds__(256, 2) stage2_kernel(
    const float* __restrict__ Wk, const float* __restrict__ bk,
    const float* __restrict__ Wv, const float* __restrict__ bv) {
    __shared__ ConvSmem S;
    const int tid = threadIdx.x;
    const int job = blockIdx.y >> 1;
    const int b   = blockIdx.y & 1;
    const int m0  = blockIdx.x * 128;
    const float* W  = job ? Wv : Wk;
    const float* bi = job ? bv : bk;
    float* dstb = (job ? g_v : g_k) + b * CC * NN;
    const float* srcb = g_xs + b * CC * NN;

    if (tid < 48) { S.sc_s[tid] = 1.f; S.bias_s[tid] = bi[tid]; }
    __syncthreads();
    conv_fill(S, srcb, m0, W, tid);
    __syncthreads();

    const int warp = tid >> 5, lane = tid & 31;
    const int gid = lane >> 2, tig = lane & 3;
    const int qrow = warp * 16 + gid;
    float cS[6][4];
    conv_mma(S, cS, qrow, tig, gid);

#pragma unroll
    for (int nb = 0; nb < 6; nb++) {
        int col = nb * 8 + 2 * tig;
        dstb[col * NN + m0 + qrow]           = cS[nb][0];
        dstb[(col + 1) * NN + m0 + qrow]     = cS[nb][1];
        dstb[col * NN + m0 + qrow + 8]       = cS[nb][2];
        dstb[(col + 1) * NN + m0 + qrow + 8] = cS[nb][3];
    }
}

// ---------------- offset head + position + grid-sample x (512 thr) --------------
__global__ void deform_kernel(const float* __restrict__ x,
                              const float* __restrict__ dww, const float* __restrict__ dwb,
                              const float* __restrict__ lng, const float* __restrict__ lnb,
                              const float* __restrict__ pww) {
    int b = blockIdx.y;
    int y = blockIdx.x;
    int tid = threadIdx.x;
    __shared__ float ts[CC * WW];
    __shared__ float posr[WW * 2];
    __shared__ float redA[8][WW];
    __shared__ float redB[8][WW];

    for (int i = tid; i < CC * WW; i += 512) {
        int c = i >> 6, px = i & 63;
        float acc = dwb[c];
        const float* qc = g_q + (b * CC + c) * NN;
        const float* wc = dww + c * 9;
#pragma unroll
        for (int ky = 0; ky < 3; ky++) {
            int yy = y + ky - 1;
            if (yy < 0 || yy > 63) continue;
#pragma unroll
            for (int kx = 0; kx < 3; kx++) {
                int xx = px + kx - 1;
                if (xx < 0 || xx > 63) continue;
                acc += qc[(yy << 6) + xx] * wc[ky * 3 + kx];
            }
        }
        ts[c * 64 + px] = acc;
    }
    __syncthreads();

    const int sub = tid >> 6;
    const int px  = tid & 63;
    {
        float s = 0.f;
#pragma unroll
        for (int j = 0; j < 6; j++) s += ts[(sub * 6 + j) * 64 + px];
        redA[sub][px] = s;
    }
    __syncthreads();
    float mu = 0.f;
#pragma unroll
    for (int u = 0; u < 8; u++) mu += redA[u][px];
    mu *= (1.f / 48.f);
    {
        float v2 = 0.f;
#pragma unroll
        for (int j = 0; j < 6; j++) {
            float d = ts[(sub * 6 + j) * 64 + px] - mu;
            v2 += d * d;
        }
        redB[sub][px] = v2;
    }
    __syncthreads();
    float var = 0.f;
#pragma unroll
    for (int u = 0; u < 8; u++) var += redB[u][px];
    float rs = rsqrtf(var * (1.f / 48.f) + 1e-5f);
    {
        float a0 = 0.f, a1 = 0.f;
#pragma unroll
        for (int j = 0; j < 6; j++) {
            int c = sub * 6 + j;
            float v = (ts[c * 64 + px] - mu) * rs * lng[c] + lnb[c];
            v = 0.5f * v * (1.f + erff(v * 0.7071067811865475f));
            a0 += pww[c] * v;
            a1 += pww[CC + c] * v;
        }
        redA[sub][px] = a0;
        redB[sub][px] = a1;
    }
    __syncthreads();
    if (tid < WW) {
        float a0 = 0.f, a1 = 0.f;
#pragma unroll
        for (int u = 0; u < 8; u++) { a0 += redA[u][px]; a1 += redB[u][px]; }
        float py  = tanhf(a0) * (2.f / 63.f) + ((0.5f + (float)y ) * (2.f / 63.f) - 1.f);
        float pxx = tanhf(a1) * (2.f / 63.f) + ((0.5f + (float)px) * (2.f / 63.f) - 1.f);
        posr[px * 2 + 0] = py;
        posr[px * 2 + 1] = pxx;
        int n = (y << 6) + px;
        g_pos[(b * NN + n) * 2 + 0] = py;
        g_pos[(b * NN + n) * 2 + 1] = pxx;
    }
    __syncthreads();

    for (int i = tid; i < CC * WW; i += 512) {
        int c = i >> 6, p = i & 63;
        float py  = posr[p * 2 + 0];
        float pxx = posr[p * 2 + 1];
        float gx = (pxx + 1.f) * 0.5f * 63.f;
        float gy = (py  + 1.f) * 0.5f * 63.f;
        const float* img = x + (b * CC + c) * NN;
        float x0f = floorf(gx), y0f = floorf(gy);
        int   x0 = (int)x0f, y0 = (int)y0f;
        float wx = gx - x0f, wy = gy - y0f;
        float acc = 0.f;
#pragma unroll
        for (int dy = 0; dy < 2; dy++) {
            int yc = y0 + dy;
            if (yc < 0 || yc >= HH) continue;
            float wyv = dy ? wy : (1.f - wy);
#pragma unroll
            for (int dx = 0; dx < 2; dx++) {
                int xc = x0 + dx;
                if (xc < 0 || xc >= WW) continue;
                float wxv = dx ? wx : (1.f - wx);
                acc += img[yc * WW + xc] * (wyv * wxv);
            }
        }
        g_xs[(b * CC + c) * NN + (y << 6) + p] = acc;
    }
}

// ---------------- bias precompute: g_bias[b][n][m] -------------------------------
// grid (NN/8, BB), 256 threads = 8 warps; warp owns key n = blockIdx.x*8 + warp.
// For each query row y: y-interp once, then lanes sweep 64 query columns
// (coalesced LDG.128 gathers + perfectly coalesced STG.32 along m).
__global__ void __launch_bounds__(256) bias_kernel() {
    const int b    = blockIdx.y;
    const int warp = threadIdx.x >> 5;
    const int lane = threadIdx.x & 31;
    const int n    = blockIdx.x * 8 + warp;

    const float step = 95.0f / 63.0f;
    float py = g_pos[(b * NN + n) * 2 + 0];
    float px = g_pos[(b * NN + n) * 2 + 1];
    float kbx = 47.5f * px;
    float* dst = g_bias + ((size_t)b * NN + n) * NN;

    // x-lerp data is lane-invariant per iteration pair; precompute per-lane gx parts
    float gx0 = 47.5f + (float)lane * step - kbx;          // m-col = lane
    float gx1 = 47.5f + (float)(lane + 32) * step - kbx;   // m-col = lane+32

    for (int y = 0; y < HH; y++) {
        float gy = 47.5f + (float)y * step - 47.5f * py;
        float yf = floorf(gy);
        int   iy = (int)yf;
        float fy = gy - yf;
        iy = min(max(iy, -2), 191);
        const float4* row = g_rpe4 + (iy + 2) * RP_STRIDE;

        {
            float xf = floorf(gx0);
            float fx = gx0 - xf;
            int   xi = (int)xf;
            xi = min(max(xi, -2), 192);
            float4 q4 = row[xi + 2];
            float b0 = fmaf(fx, q4.z - q4.x, q4.x);
            float b1 = fmaf(fx, q4.w - q4.y, q4.y);
            dst[y * 64 + lane] = fmaf(fy, b1 - b0, b0);
        }
        {
            float xf = floorf(gx1);
            float fx = gx1 - xf;
            int   xi = (int)xf;
            xi = min(max(xi, -2), 192);
            float4 q4 = row[xi + 2];
            float b0 = fmaf(fx, q4.z - q4.x, q4.x);
            float b1 = fmaf(fx, q4.w - q4.y, q4.y);
            dst[y * 64 + lane + 32] = fmaf(fy, b1 - b0, b0);
        }
    }
}

// ---------------- fused flash attention: tf32 MMA, bias from global --------------
#define AOF_QS 0                        // 128 x 52
#define AOF_KS (AOF_QS + 128*52)        // 48 x 64 swizzled
#define AOF_VS (AOF_KS + 48*64)         // 64 x 56
#define AOF_PS (AOF_VS + 64*56)         // 128 x 66 (P only)
#define ATTN_SMEM_FLOATS (AOF_PS + 128*66)
#define ATTN_SMEM_BYTES (ATTN_SMEM_FLOATS * 4)

__global__ void __launch_bounds__(256, 2) attn_kernel() {
    extern __shared__ float sm[];
    float* Qs = sm + AOF_QS;
    float* Ks = sm + AOF_KS;
    float* Vs = sm + AOF_VS;
    float* Ps = sm + AOF_PS;
    const uint32_t* Qu = (const uint32_t*)Qs;
    const uint32_t* Ku = (const uint32_t*)Ks;
    const uint32_t* Vu = (const uint32_t*)Vs;
    const uint32_t* Pu = (const uint32_t*)Ps;

    const int yb    = blockIdx.x;
    const int split = blockIdx.y;
    const int b     = blockIdx.z;
    const int tid   = threadIdx.x;
    const int warp  = tid >> 5;
    const int lane  = tid & 31;
    const int gid   = lane >> 2;
    const int tig   = lane & 3;
    const int m0    = yb * 128;
    const int qrow  = warp * 16 + gid;

    const float scale = 0.14433756729740643f;

    for (int i = tid; i < CC * 128; i += 256) {
        int c = i >> 7, m = i & 127;
        Qs[m * 52 + c] = __uint_as_float(f2tf(g_q[(b * CC + c) * NN + m0 + m] * scale));
    }

    float rmax0 = -1e30f, rmax1 = -1e30f, rsum0 = 0.f, rsum1 = 0.f;
    float o[6][4];
#pragma unroll
    for (int nb = 0; nb < 6; nb++)
#pragma unroll
        for (int j = 0; j < 4; j++) o[nb][j] = 0.f;

    const int nbase = split * KEYS_PER_SPLIT;
    const float* biasb = g_bias + (size_t)b * NN * NN;
    for (int t = 0; t < KEYS_PER_SPLIT / 64; t++) {
        const int n0 = nbase + t * 64;
        __syncthreads();      // prev PV done with Ps/Vs; Ks free

        // K tile swizzled
        for (int i = tid; i < CC * 64; i += 256) {
            int c = i >> 6, n = i & 63;
            Ks[c * 64 + (n ^ ((c & 3) << 3))] =
                __uint_as_float(f2tf(g_k[(b * CC + c) * NN + n0 + n]));
        }
        // V tile [n][56]
        for (int i = tid; i < CC * 64; i += 256) {
            int c = i >> 6, n = i & 63;
            Vs[n * 56 + c] = __uint_as_float(f2tf(g_v[(b * CC + c) * NN + n0 + n]));
        }

        // C-init from global bias (independent of smem; overlaps fills)
        float cS[8][4];
#pragma unroll
        for (int nb = 0; nb < 8; nb++) {
            int col = n0 + nb * 8 + 2 * tig;
            const float* r0 = biasb + (size_t)col * NN + m0;
            const float* r1 = r0 + NN;
            cS[nb][0] = r0[qrow];
            cS[nb][1] = r1[qrow];
            cS[nb][2] = r0[qrow + 8];
            cS[nb][3] = r1[qrow + 8];
        }
        __syncthreads();

        // ---- S = QK^T + bias ----
#pragma unroll
        for (int kb = 0; kb < 6; kb++) {
            uint32_t a0 = Qu[qrow * 52 + kb * 8 + tig];
            uint32_t a1 = Qu[(qrow + 8) * 52 + kb * 8 + tig];
            uint32_t a2 = Qu[qrow * 52 + kb * 8 + tig + 4];
            uint32_t a3 = Qu[(qrow + 8) * 52 + kb * 8 + tig + 4];
            const int sw = tig << 3;
#pragma unroll
            for (int nb = 0; nb < 8; nb++) {
                uint32_t b0 = Ku[(kb * 8 + tig) * 64 + ((nb * 8 + gid) ^ sw)];
                uint32_t b1 = Ku[(kb * 8 + tig + 4) * 64 + ((nb * 8 + gid) ^ sw)];
                mma_tf32(cS[nb], a0, a1, a2, a3, b0, b1);
            }
        }

        // ---- online softmax ----
        float tmax0 = -1e30f, tmax1 = -1e30f;
#pragma unroll
        for (int nb = 0; nb < 8; nb++) {
            tmax0 = fmaxf(tmax0, fmaxf(cS[nb][0], cS[nb][1]));
            tmax1 = fmaxf(tmax1, fmaxf(cS[nb][2], cS[nb][3]));
        }
        tmax0 = fmaxf(tmax0, __shfl_xor_sync(0xffffffffu, tmax0, 1));
        tmax0 = fmaxf(tmax0, __shfl_xor_sync(0xffffffffu, tmax0, 2));
        tmax1 = fmaxf(tmax1, __shfl_xor_sync(0xffffffffu, tmax1, 1));
        tmax1 = fmaxf(tmax1, __shfl_xor_sync(0xffffffffu, tmax1, 2));
        float nmax0 = fmaxf(rmax0, tmax0);
        float nmax1 = fmaxf(rmax1, tmax1);
        float f0 = __expf(rmax0 - nmax0);
        float f1 = __expf(rmax1 - nmax1);
        rmax0 = nmax0; rmax1 = nmax1;

        float psum0 = 0.f, psum1 = 0.f;
#pragma unroll
        for (int nb = 0; nb < 8; nb++) {
            float p0 = __expf(cS[nb][0] - nmax0);
            float p1 = __expf(cS[nb][1] - nmax0);
            float p2 = __expf(cS[nb][2] - nmax1);
            float p3 = __expf(cS[nb][3] - nmax1);
            psum0 += p0 + p1;
            psum1 += p2 + p3;
            int col = nb * 8 + 2 * tig;
            float2 w0 = make_float2(__uint_as_float(f2tf(p0)), __uint_as_float(f2tf(p1)));
            float2 w1 = make_float2(__uint_as_float(f2tf(p2)), __uint_as_float(f2tf(p3)));
            *(float2*)&Ps[qrow * 66 + col]       = w0;
            *(float2*)&Ps[(qrow + 8) * 66 + col] = w1;
        }
        psum0 += __shfl_xor_sync(0xffffffffu, psum0, 1);
        psum0 += __shfl_xor_sync(0xffffffffu, psum0, 2);
        psum1 += __shfl_xor_sync(0xffffffffu, psum1, 1);
        psum1 += __shfl_xor_sync(0xffffffffu, psum1, 2);
        rsum0 = rsum0 * f0 + psum0;
        rsum1 = rsum1 * f1 + psum1;

#pragma unroll
        for (int nb = 0; nb < 6; nb++) {
            o[nb][0] *= f0; o[nb][1] *= f0;
            o[nb][2] *= f1; o[nb][3] *= f1;
        }
        __syncthreads();

        // ---- PV: O += P x V ----
#pragma unroll
        for (int kb = 0; kb < 8; kb++) {
            uint32_t a0 = Pu[qrow * 66 + kb * 8 + tig];
            uint32_t a1 = Pu[(qrow + 8) * 66 + kb * 8 + tig];
            uint32_t a2 = Pu[qrow * 66 + kb * 8 + tig + 4];
            uint32_t a3 = Pu[(qrow + 8) * 66 + kb * 8 + tig + 4];
#pragma unroll
            for (int nb = 0; nb < 6; nb++) {
                uint32_t b0 = Vu[(kb * 8 + tig) * 56 + nb * 8 + gid];
                uint32_t b1 = Vu[(kb * 8 + tig + 4) * 56 + nb * 8 + gid];
                mma_tf32(o[nb], a0, a1, a2, a3, b0, b1);
            }
        }
    }

    const int mA = m0 + qrow;
    const int mB = mA + 8;
    float* op = g_opart + (split * BB + b) * CC * NN;
#pragma unroll
    for (int nb = 0; nb < 6; nb++) {
        int ch = nb * 8 + 2 * tig;
        op[ch * NN + mA]       = o[nb][0];
        op[(ch + 1) * NN + mA] = o[nb][1];
        op[ch * NN + mB]       = o[nb][2];
        op[(ch + 1) * NN + mB] = o[nb][3];
    }
    if (tig == 0) {
        g_mpart[(split * BB + b) * NN + mA] = rmax0;
        g_mpart[(split * BB + b) * NN + mB] = rmax1;
        g_lpart[(split * BB + b) * NN + mA] = rsum0;
        g_lpart[(split * BB + b) * NN + mB] = rsum1;
    }
}

// ---------------- window attention: 4 windows per 256-thread block --------------
__global__ void __launch_bounds__(256, 4) winattn_kernel() {
    int b  = blockIdx.z;
    int sp = blockIdx.y;
    int wg = threadIdx.x >> 6;
    int w  = blockIdx.x * 4 + wg;
    int t  = threadIdx.x & 63;

    __shared__ float qsm[4][64][17];
    __shared__ float vsm[4][64][17];

    int py, px;
    if (sp == 0)      { int wy = w >> 3, wx = w & 7; py = wy * 8 + (t >> 3); px = wx * 8 + (t & 7); }
    else if (sp == 1) { py = t;  px = w; }
    else              { py = w;  px = t; }
    int pix = py * 64 + px;

    int qbase = (b * 96 + sp * 32) * NN + pix;
#pragma unroll
    for (int c = 0; c < 16; c++) {
        qsm[wg][t][c] = g_x2[qbase + c * NN];
        vsm[wg][t][c] = g_x2[qbase + (16 + c) * NN];
    }
    __syncthreads();

    float qr[16];
#pragma unroll
    for (int c = 0; c < 16; c++) qr[c] = qsm[wg][t][c];

    float lg[64];
    float mx = -1e30f;
    for (int j = 0; j < 64; j++) {
        float d = 0.f;
#pragma unroll
        for (int c = 0; c < 16; c++) d += qr[c] * qsm[wg][j][c];
        lg[j] = d;
        mx = fmaxf(mx, d);
    }
    float s = 0.f;
    for (int j = 0; j < 64; j++) { lg[j] = __expf(lg[j] - mx); s += lg[j]; }
    float inv = 1.f / s;

    float o[16];
#pragma unroll
    for (int c = 0; c < 16; c++) o[c] = 0.f;
    for (int j = 0; j < 64; j++) {
        float p = lg[j] * inv;
#pragma unroll
        for (int c = 0; c < 16; c++) o[c] += p * vsm[wg][j][c];
    }
#pragma unroll
    for (int c = 0; c < 16; c++)
        g_win[(b * CC + sp * 16 + c) * NN + pix] = o[c];
}

// ---------------- final: MMA pout conv + split merge + average -------------------
__global__ void __launch_bounds__(256, 2) final_kernel(
    const float* __restrict__ pw, const float* __restrict__ pb,
    float* __restrict__ out) {
    __shared__ ConvSmem S;
    const int tid = threadIdx.x;
    const int b   = blockIdx.y;
    const int m0  = blockIdx.x * 128;

    if (tid < 48) { S.sc_s[tid] = 1.f; S.bias_s[tid] = pb[tid]; }
    __syncthreads();
    conv_fill(S, g_win + b * CC * NN, m0, pw, tid);
    __syncthreads();

    const int warp = tid >> 5, lane = tid & 31;
    const int gid = lane >> 2, tig = lane & 3;
    const int qrow = warp * 16 + gid;
    float cS[6][4];
    conv_mma(S, cS, qrow, tig, gid);

    const int mA = m0 + qrow;
    const int mB = mA + 8;

    float eA[NSPLIT], eB[NSPLIT];
    {
        float MA = -1e30f, MB = -1e30f;
        float mvA[NSPLIT], mvB[NSPLIT];
#pragma unroll
        for (int s = 0; s < NSPLIT; s++) {
            mvA[s] = g_mpart[(s * BB + b) * NN + mA];
            mvB[s] = g_mpart[(s * BB + b) * NN + mB];
            MA = fmaxf(MA, mvA[s]); MB = fmaxf(MB, mvB[s]);
        }
        float lA = 0.f, lB = 0.f;
#pragma unroll
        for (int s = 0; s < NSPLIT; s++) {
            eA[s] = __expf(mvA[s] - MA);
            eB[s] = __expf(mvB[s] - MB);
            lA += g_lpart[(s * BB + b) * NN + mA] * eA[s];
            lB += g_lpart[(s * BB + b) * NN + mB] * eB[s];
        }
        float ilA = 0.5f / lA, ilB = 0.5f / lB;
#pragma unroll
        for (int s = 0; s < NSPLIT; s++) { eA[s] *= ilA; eB[s] *= ilB; }
    }

#pragma unroll
    for (int nb = 0; nb < 6; nb++) {
        int col = nb * 8 + 2 * tig;
#pragma unroll
        for (int j = 0; j < 2; j++) {
            int ch = col + j;
            float odA = 0.f, odB = 0.f;
#pragma unroll
            for (int s = 0; s < NSPLIT; s++) {
                odA += g_opart[((s * BB + b) * CC + ch) * NN + mA] * eA[s];
                odB += g_opart[((s * BB + b) * CC + ch) * NN + mB] * eB[s];
            }
            out[(b * CC + ch) * NN + mA] = 0.5f * cS[nb][j]     + odA;
            out[(b * CC + ch) * NN + mB] = 0.5f * cS[nb][2 + j] + odB;
        }
    }
}

// ---------------- launch ---------------------------------------------------------
extern "C" void kernel_launch(void* const* d_in, const int* in_sizes, int n_in,
                              void* d_out, int out_size) {
    const float* x        = (const float*)d_in[0];
    const float* Wq       = (const float*)d_in[1];
    const float* bq       = (const float*)d_in[2];
    const float* off_dw_w = (const float*)d_in[3];
    const float* off_dw_b = (const float*)d_in[4];
    const float* off_ln_g = (const float*)d_in[5];
    const float* off_ln_b = (const float*)d_in[6];
    const float* off_pw_w = (const float*)d_in[7];
    const float* Wk       = (const float*)d_in[8];
    const float* bk       = (const float*)d_in[9];
    const float* Wv       = (const float*)d_in[10];
    const float* bv       = (const float*)d_in[11];
    const float* inp_w    = (const float*)d_in[12];
    const float* inp_b    = (const float*)d_in[13];
    const float* bn_g     = (const float*)d_in[14];
    const float* bn_b     = (const float*)d_in[15];
    const float* bn_mean  = (const float*)d_in[16];
    const float* bn_var   = (const float*)d_in[17];
    const float* pout_w   = (const float*)d_in[18];
    const float* pout_b   = (const float*)d_in[19];
    const float* rpe      = (const float*)d_in[20];
    float* out = (float*)d_out;

    cudaFuncSetAttribute(attn_kernel, cudaFuncAttributeMaxDynamicSharedMemorySize,
                         ATTN_SMEM_BYTES);

    stage1_kernel<<<dim3(32, 7), 256>>>(x, Wq, bq, inp_w, inp_b,
                                        bn_g, bn_b, bn_mean, bn_var, rpe);
    deform_kernel<<<dim3(HH, BB), 512>>>(x, off_dw_w, off_dw_b,
                                         off_ln_g, off_ln_b, off_pw_w);
    bias_kernel<<<dim3(NN / 8, BB), 256>>>();
    stage2_kernel<<<dim3(32, 4), 256>>>(Wk, bk, Wv, bv);
    attn_kernel<<<dim3(NN / 128, NSPLIT, BB), 256, ATTN_SMEM_BYTES>>>();
    winattn_kernel<<<dim3(16, 3, BB), 256>>>();
    final_kernel<<<dim3(32, BB), 256>>>(pout_w, pout_b, out);
}

// round 13
// speedup vs baseline: 1.2943x; 1.2938x over previous
#include <cuda_runtime.h>
#include <cuda_bf16.h>
#include <math.h>
#include <stdint.h>

// Problem constants
#define BB 2
#define CC 48
#define HH 64
#define WW 64
#define NN 4096
#define RPE_S 191
#define NSPLIT 4
#define KEYS_PER_SPLIT (NN / NSPLIT)

#define RP_ROWS 194
#define RP_STRIDE 196

// ---------------- scratch (device globals; no allocation allowed) -------------
__device__ float  g_q  [BB*CC*NN];
__device__ float  g_x2 [BB*96*NN];
__device__ float  g_pos[BB*NN*2];
__device__ float  g_xs [BB*CC*NN];
__device__ float  g_k  [BB*CC*NN];
__device__ float  g_v  [BB*CC*NN];
__device__ float  g_win[BB*CC*NN];
__device__ float  g_opart[NSPLIT*BB*CC*NN];
__device__ float  g_mpart[NSPLIT*BB*NN];
__device__ float  g_lpart[NSPLIT*BB*NN];
__device__ float4 g_rpe4[RP_ROWS*RP_STRIDE];

// ---------------- MMA helpers -----------------------------------------------------
__device__ __forceinline__ uint32_t f2tf(float f) {
    uint32_t r; asm("cvt.rna.tf32.f32 %0, %1;" : "=r"(r) : "f"(f)); return r;
}
__device__ __forceinline__ void mma_tf32(float* c,
                                         uint32_t a0, uint32_t a1, uint32_t a2, uint32_t a3,
                                         uint32_t b0, uint32_t b1) {
    asm("mma.sync.aligned.m16n8k8.row.col.f32.tf32.tf32.f32 "
        "{%0,%1,%2,%3}, {%4,%5,%6,%7}, {%8,%9}, {%0,%1,%2,%3};"
        : "+f"(c[0]), "+f"(c[1]), "+f"(c[2]), "+f"(c[3])
        : "r"(a0), "r"(a1), "r"(a2), "r"(a3), "r"(b0), "r"(b1));
}
__device__ __forceinline__ void mma_bf16(float* c,
                                         uint32_t a0, uint32_t a1, uint32_t a2, uint32_t a3,
                                         uint32_t b0, uint32_t b1) {
    asm("mma.sync.aligned.m16n8k16.row.col.f32.bf16.bf16.f32 "
        "{%0,%1,%2,%3}, {%4,%5,%6,%7}, {%8,%9}, {%0,%1,%2,%3};"
        : "+f"(c[0]), "+f"(c[1]), "+f"(c[2]), "+f"(c[3])
        : "r"(a0), "r"(a1), "r"(a2), "r"(a3), "r"(b0), "r"(b1));
}
__device__ __forceinline__ uint32_t packbf(float lo, float hi) {
    __nv_bfloat162 h = __floats2bfloat162_rn(lo, hi);   // .x = lo (low 16 bits)
    return *(uint32_t*)&h;
}

// ---------------- shared 48x48 GEMM tile (128 pixels per block) -------------------
struct ConvSmem {
    float Xs[128 * 52];
    float Ws[48 * 64];
    float bias_s[48];
    float sc_s[48];
};

__device__ __forceinline__ void conv_fill(ConvSmem& S, const float* __restrict__ srcb,
                                          int m0, const float* __restrict__ W, int tid) {
    for (int i = tid; i < CC * 128; i += 256) {
        int c = i >> 7, m = i & 127;
        S.Xs[m * 52 + c] = __uint_as_float(f2tf(srcb[c * NN + m0 + m]));
    }
    for (int i = tid; i < 48 * 64; i += 256) {
        int c = i >> 6, o = i & 63;
        float v = (o < 48) ? W[o * CC + c] * S.sc_s[o] : 0.f;
        S.Ws[c * 64 + (o ^ ((c & 3) << 3))] = __uint_as_float(f2tf(v));
    }
}

__device__ __forceinline__ void conv_mma(const ConvSmem& S, float cS[6][4],
                                         int qrow, int tig, int gid) {
    const uint32_t* Xu = (const uint32_t*)S.Xs;
    const uint32_t* Wu = (const uint32_t*)S.Ws;
#pragma unroll
    for (int nb = 0; nb < 6; nb++) {
        int col = nb * 8 + 2 * tig;
        cS[nb][0] = cS[nb][2] = S.bias_s[col];
        cS[nb][1] = cS[nb][3] = S.bias_s[col + 1];
    }
    const int sw = tig << 3;
#pragma unroll
    for (int kb = 0; kb < 6; kb++) {
        uint32_t a0 = Xu[qrow * 52 + kb * 8 + tig];
        uint32_t a1 = Xu[(qrow + 8) * 52 + kb * 8 + tig];
        uint32_t a2 = Xu[qrow * 52 + kb * 8 + tig + 4];
        uint32_t a3 = Xu[(qrow + 8) * 52 + kb * 8 + tig + 4];
#pragma unroll
        for (int nb = 0; nb < 6; nb++) {
            uint32_t b0 = Wu[(kb * 8 + tig) * 64 + ((nb * 8 + gid) ^ sw)];
            uint32_t b1 = Wu[(kb * 8 + tig + 4) * 64 + ((nb * 8 + gid) ^ sw)];
            mma_tf32(cS[nb], a0, a1, a2, a3, b0, b1);
        }
    }
}

// ---------------- stage1: q + x2(BN) projections + rpe quad-pack -----------------
__global__ void __launch_bounds__(256, 2) stage1_kernel(
    const float* __restrict__ x,
    const float* __restrict__ Wq, const float* __restrict__ bq,
    const float* __restrict__ inp_w, const float* __restrict__ inp_b,
    const float* __restrict__ bng, const float* __restrict__ bnb,
    const float* __restrict__ bnm, const float* __restrict__ bnv,
    const float* __restrict__ rpe) {
    const int tid = threadIdx.x;
    if (blockIdx.y == 6) {
        for (int idx = blockIdx.x * 256 + tid; idx < RP_ROWS * RP_STRIDE; idx += 32 * 256) {
            int r  = idx / RP_STRIDE;
            int xc = idx - r * RP_STRIDE;
            int yy = r - 2, xx = xc - 2;
            float v00 = 0.f, v10 = 0.f, v01 = 0.f, v11 = 0.f;
            bool y0ok = (yy     >= 0 && yy     <= 190);
            bool y1ok = (yy + 1 >= 0 && yy + 1 <= 190);
            if (xx >= 0 && xx <= 190) {
                if (y0ok) v00 = rpe[yy * RPE_S + xx];
                if (y1ok) v10 = rpe[(yy + 1) * RPE_S + xx];
            }
            if (xx + 1 >= 0 && xx + 1 <= 190) {
                if (y0ok) v01 = rpe[yy * RPE_S + xx + 1];
                if (y1ok) v11 = rpe[(yy + 1) * RPE_S + xx + 1];
            }
            g_rpe4[idx] = make_float4(v00, v10, v01, v11);
        }
        return;
    }
    __shared__ ConvSmem S;
    const int job = blockIdx.y >> 1;
    const int b   = blockIdx.y & 1;
    const int m0  = blockIdx.x * 128;

    const float* W;
    const float* bi;
    const float* srcb = x + b * CC * NN;
    float* dstb;
    int bnoff = -1;
    if (job == 0)      { W = Wq;              bi = bq;          dstb = g_q  + b * CC * NN; }
    else if (job == 1) { W = inp_w;           bi = inp_b;       dstb = g_x2 + b * 96 * NN;            bnoff = 0;  }
    else               { W = inp_w + 48 * CC; bi = inp_b + 48;  dstb = g_x2 + (b * 96 + 48) * NN;     bnoff = 48; }

    if (tid < 48) {
        if (bnoff < 0) { S.sc_s[tid] = 1.f; S.bias_s[tid] = bi[tid]; }
        else {
            float sc = rsqrtf(bnv[bnoff + tid] + 1e-5f) * bng[bnoff + tid];
            S.sc_s[tid]   = sc;
            S.bias_s[tid] = (bi[tid] - bnm[bnoff + tid]) * sc + bnb[bnoff + tid];
        }
    }
    __syncthreads();
    conv_fill(S, srcb, m0, W, tid);
    __syncthreads();

    const int warp = tid >> 5, lane = tid & 31;
    const int gid = lane >> 2, tig = lane & 3;
    const int qrow = warp * 16 + gid;
    float cS[6][4];
    conv_mma(S, cS, qrow, tig, gid);

#pragma unroll
    for (int nb = 0; nb < 6; nb++) {
        int col = nb * 8 + 2 * tig;
        dstb[col * NN + m0 + qrow]           = cS[nb][0];
        dstb[(col + 1) * NN + m0 + qrow]     = cS[nb][1];
        dstb[col * NN + m0 + qrow + 8]       = cS[nb][2];
        dstb[(col + 1) * NN + m0 + qrow + 8] = cS[nb][3];
    }
}

// ---------------- stage2: k,v projections -----------------------------------------
__global__ void __launch_bounds__(256, 2) stage2_kernel(
    const float* __restrict__ Wk, const float* __restrict__ bk,
    const float* __restrict__ Wv, const float* __restrict__ bv) {
    __shared__ ConvSmem S;
    const int tid = threadIdx.x;
    const int job = blockIdx.y >> 1;
    const int b   = blockIdx.y & 1;
    const int m0  = blockIdx.x * 128;
    const float* W  = job ? Wv : Wk;
    const float* bi = job ? bv : bk;
    float* dstb = (job ? g_v : g_k) + b * CC * NN;
    const float* srcb = g_xs + b * CC * NN;

    if (tid < 48) { S.sc_s[tid] = 1.f; S.bias_s[tid] = bi[tid]; }
    __syncthreads();
    conv_fill(S, srcb, m0, W, tid);
    __syncthreads();

    const int warp = tid >> 5, lane = tid & 31;
    const int gid = lane >> 2, tig = lane & 3;
    const int qrow = warp * 16 + gid;
    float cS[6][4];
    conv_mma(S, cS, qrow, tig, gid);

#pragma unroll
    for (int nb = 0; nb < 6; nb++) {
        int col = nb * 8 + 2 * tig;
        dstb[col * NN + m0 + qrow]           = cS[nb][0];
        dstb[(col + 1) * NN + m0 + qrow]     = cS[nb][1];
        dstb[col * NN + m0 + qrow + 8]       = cS[nb][2];
        dstb[(col + 1) * NN + m0 + qrow + 8] = cS[nb][3];
    }
}

// ---------------- offset head + position + grid-sample x (512 thr) --------------
__global__ void deform_kernel(const float* __restrict__ x,
                              const float* __restrict__ dww, const float* __restrict__ dwb,
                              const float* __restrict__ lng, const float* __restrict__ lnb,
                              const float* __restrict__ pww) {
    int b = blockIdx.y;
    int y = blockIdx.x;
    int tid = threadIdx.x;
    __shared__ float ts[CC * WW];
    __shared__ float posr[WW * 2];
    __shared__ float redA[8][WW];
    __shared__ float redB[8][WW];

    for (int i = tid; i < CC * WW; i += 512) {
        int c = i >> 6, px = i & 63;
        float acc = dwb[c];
        const float* qc = g_q + (b * CC + c) * NN;
        const float* wc = dww + c * 9;
#pragma unroll
        for (int ky = 0; ky < 3; ky++) {
            int yy = y + ky - 1;
            if (yy < 0 || yy > 63) continue;
#pragma unroll
            for (int kx = 0; kx < 3; kx++) {
                int xx = px + kx - 1;
                if (xx < 0 || xx > 63) continue;
                acc += qc[(yy << 6) + xx] * wc[ky * 3 + kx];
            }
        }
        ts[c * 64 + px] = acc;
    }
    __syncthreads();

    const int sub = tid >> 6;
    const int px  = tid & 63;
    {
        float s = 0.f;
#pragma unroll
        for (int j = 0; j < 6; j++) s += ts[(sub * 6 + j) * 64 + px];
        redA[sub][px] = s;
    }
    __syncthreads();
    float mu = 0.f;
#pragma unroll
    for (int u = 0; u < 8; u++) mu += redA[u][px];
    mu *= (1.f / 48.f);
    {
        float v2 = 0.f;
#pragma unroll
        for (int j = 0; j < 6; j++) {
            float d = ts[(sub * 6 + j) * 64 + px] - mu;
            v2 += d * d;
        }
        redB[sub][px] = v2;
    }
    __syncthreads();
    float var = 0.f;
#pragma unroll
    for (int u = 0; u < 8; u++) var += redB[u][px];
    float rs = rsqrtf(var * (1.f / 48.f) + 1e-5f);
    {
        float a0 = 0.f, a1 = 0.f;
#pragma unroll
        for (int j = 0; j < 6; j++) {
            int c = sub * 6 + j;
            float v = (ts[c * 64 + px] - mu) * rs * lng[c] + lnb[c];
            v = 0.5f * v * (1.f + erff(v * 0.7071067811865475f));
            a0 += pww[c] * v;
            a1 += pww[CC + c] * v;
        }
        redA[sub][px] = a0;
        redB[sub][px] = a1;
    }
    __syncthreads();
    if (tid < WW) {
        float a0 = 0.f, a1 = 0.f;
#pragma unroll
        for (int u = 0; u < 8; u++) { a0 += redA[u][px]; a1 += redB[u][px]; }
        float py  = tanhf(a0) * (2.f / 63.f) + ((0.5f + (float)y ) * (2.f / 63.f) - 1.f);
        float pxx = tanhf(a1) * (2.f / 63.f) + ((0.5f + (float)px) * (2.f / 63.f) - 1.f);
        posr[px * 2 + 0] = py;
        posr[px * 2 + 1] = pxx;
        int n = (y << 6) + px;
        g_pos[(b * NN + n) * 2 + 0] = py;
        g_pos[(b * NN + n) * 2 + 1] = pxx;
    }
    __syncthreads();

    for (int i = tid; i < CC * WW; i += 512) {
        int c = i >> 6, p = i & 63;
        float py  = posr[p * 2 + 0];
        float pxx = posr[p * 2 + 1];
        float gx = (pxx + 1.f) * 0.5f * 63.f;
        float gy = (py  + 1.f) * 0.5f * 63.f;
        const float* img = x + (b * CC + c) * NN;
        float x0f = floorf(gx), y0f = floorf(gy);
        int   x0 = (int)x0f, y0 = (int)y0f;
        float wx = gx - x0f, wy = gy - y0f;
        float acc = 0.f;
#pragma unroll
        for (int dy = 0; dy < 2; dy++) {
            int yc = y0 + dy;
            if (yc < 0 || yc >= HH) continue;
            float wyv = dy ? wy : (1.f - wy);
#pragma unroll
            for (int dx = 0; dx < 2; dx++) {
                int xc = x0 + dx;
                if (xc < 0 || xc >= WW) continue;
                float wxv = dx ? wx : (1.f - wx);
                acc += img[yc * WW + xc] * (wyv * wxv);
            }
        }
        g_xs[(b * CC + c) * NN + (y << 6) + p] = acc;
    }
}

// ---------------- fused flash attention: tf32 QK + bf16 PV ------------------------
// smem: Qs 128x52 f32, Ks 48x64 f32 swizzled, Vp 48x36 u32 (bf16x2 pairs along n),
//       Pp 128x36 u32 (bf16x2 pairs along n), BiasS 128x66 f32. Total 98048 B.
#define AOF_QS 0
#define AOF_KS (AOF_QS + 128*52)
#define AOF_VP (AOF_KS + 48*64)
#define AOF_PP (AOF_VP + 48*36)
#define AOF_BS (AOF_PP + 128*36)
#define ATTN_SMEM_FLOATS (AOF_BS + 128*66)
#define ATTN_SMEM_BYTES (ATTN_SMEM_FLOATS * 4)

__global__ void __launch_bounds__(256, 2) attn_kernel() {
    extern __shared__ float sm[];
    float*    Qs = sm + AOF_QS;
    float*    Ks = sm + AOF_KS;
    uint32_t* Vp = (uint32_t*)(sm + AOF_VP);
    uint32_t* Pp = (uint32_t*)(sm + AOF_PP);
    float*    Bs = sm + AOF_BS;
    const uint32_t* Qu = (const uint32_t*)Qs;
    const uint32_t* Ku = (const uint32_t*)Ks;

    const int yb    = blockIdx.x;
    const int split = blockIdx.y;
    const int b     = blockIdx.z;
    const int tid   = threadIdx.x;
    const int warp  = tid >> 5;
    const int lane  = tid & 31;
    const int gid   = lane >> 2;
    const int tig   = lane & 3;
    const int m0    = yb * 128;
    const int qrow  = warp * 16 + gid;

    const float scale = 0.14433756729740643f;
    const float step  = 95.0f / 63.0f;

    // load Q tile [m][c] (stride 52), scaled, tf32
    for (int i = tid; i < CC * 128; i += 256) {
        int c = i >> 7, m = i & 127;
        Qs[m * 52 + c] = __uint_as_float(f2tf(g_q[(b * CC + c) * NN + m0 + m] * scale));
    }

    float rmax0 = -1e30f, rmax1 = -1e30f, rsum0 = 0.f, rsum1 = 0.f;
    float o[6][4];
#pragma unroll
    for (int nb = 0; nb < 6; nb++)
#pragma unroll
        for (int j = 0; j < 4; j++) o[nb][j] = 0.f;

    const int nbase = split * KEYS_PER_SPLIT;
    for (int t = 0; t < KEYS_PER_SPLIT / 64; t++) {
        const int n0 = nbase + t * 64;
        __syncthreads();      // prev tile done with Ks/Vp/Bs (PV reads Vp/Pp)

        // K tile swizzled (tf32)
        for (int i = tid; i < CC * 64; i += 256) {
            int c = i >> 6, n = i & 63;
            Ks[c * 64 + (n ^ ((c & 3) << 3))] =
                __uint_as_float(f2tf(g_k[(b * CC + c) * NN + n0 + n]));
        }
        // V tile packed bf16 pairs along n: Vp[c][pi], pi = n/2
        for (int i = tid; i < 48 * 32; i += 256) {
            int c = i >> 5, pi = i & 31;
            float2 v2 = *(const float2*)&g_v[(b * CC + c) * NN + n0 + 2 * pi];
            Vp[c * 36 + pi] = packbf(v2.x, v2.y);
        }

        // bias -> Bs[m][n] (stride 66): warp owns 8 keys, lanes sweep queries
#pragma unroll
        for (int kk = 0; kk < 8; kk++) {
            int n = warp * 8 + kk;
            float py = g_pos[(b * NN + n0 + n) * 2 + 0];
            float px = g_pos[(b * NN + n0 + n) * 2 + 1];
            float kbx = 47.5f * px;
            float fy[2];
            const float4* row[2];
#pragma unroll
            for (int r = 0; r < 2; r++) {
                float gy = 47.5f + (float)(yb * 2 + r) * step - 47.5f * py;
                float yf = floorf(gy);
                int   iy = (int)yf;
                fy[r] = gy - yf;
                iy = min(max(iy, -2), 191);
                row[r] = g_rpe4 + (iy + 2) * RP_STRIDE;
            }
#pragma unroll
            for (int it = 0; it < 4; it++) {
                int m = it * 32 + lane;
                int r = it >> 1;
                float gx = 47.5f + (float)(m & 63) * step - kbx;
                float xf = floorf(gx);
                float fx = gx - xf;
                int   xi = (int)xf;
                xi = min(max(xi, -2), 192);
                float4 q4 = row[r][xi + 2];
                float b0 = fmaf(fx, q4.z - q4.x, q4.x);
                float b1 = fmaf(fx, q4.w - q4.y, q4.y);
                Bs[m * 66 + n] = fmaf(fy[r], b1 - b0, b0);
            }
        }
        __syncthreads();      // Ks, Vp, Bs complete

        // ---- S = QK^T + bias : C init from Bs ----
        float cS[8][4];
#pragma unroll
        for (int nb = 0; nb < 8; nb++) {
            int col = nb * 8 + 2 * tig;
            float2 bA = *(const float2*)&Bs[qrow * 66 + col];
            float2 bB = *(const float2*)&Bs[(qrow + 8) * 66 + col];
            cS[nb][0] = bA.x; cS[nb][1] = bA.y;
            cS[nb][2] = bB.x; cS[nb][3] = bB.y;
        }
#pragma unroll
        for (int kb = 0; kb < 6; kb++) {
            uint32_t a0 = Qu[qrow * 52 + kb * 8 + tig];
            uint32_t a1 = Qu[(qrow + 8) * 52 + kb * 8 + tig];
            uint32_t a2 = Qu[qrow * 52 + kb * 8 + tig + 4];
            uint32_t a3 = Qu[(qrow + 8) * 52 + kb * 8 + tig + 4];
            const int sw = tig << 3;
#pragma unroll
            for (int nb = 0; nb < 8; nb++) {
                uint32_t b0 = Ku[(kb * 8 + tig) * 64 + ((nb * 8 + gid) ^ sw)];
                uint32_t b1 = Ku[(kb * 8 + tig + 4) * 64 + ((nb * 8 + gid) ^ sw)];
                mma_tf32(cS[nb], a0, a1, a2, a3, b0, b1);
            }
        }

        // ---- online softmax ----
        float tmax0 = -1e30f, tmax1 = -1e30f;
#pragma unroll
        for (int nb = 0; nb < 8; nb++) {
            tmax0 = fmaxf(tmax0, fmaxf(cS[nb][0], cS[nb][1]));
            tmax1 = fmaxf(tmax1, fmaxf(cS[nb][2], cS[nb][3]));
        }
        tmax0 = fmaxf(tmax0, __shfl_xor_sync(0xffffffffu, tmax0, 1));
        tmax0 = fmaxf(tmax0, __shfl_xor_sync(0xffffffffu, tmax0, 2));
        tmax1 = fmaxf(tmax1, __shfl_xor_sync(0xffffffffu, tmax1, 1));
        tmax1 = fmaxf(tmax1, __shfl_xor_sync(0xffffffffu, tmax1, 2));
        float nmax0 = fmaxf(rmax0, tmax0);
        float nmax1 = fmaxf(rmax1, tmax1);
        float f0 = __expf(rmax0 - nmax0);
        float f1 = __expf(rmax1 - nmax1);
        rmax0 = nmax0; rmax1 = nmax1;

        float psum0 = 0.f, psum1 = 0.f;
#pragma unroll
        for (int nb = 0; nb < 8; nb++) {
            float p0 = __expf(cS[nb][0] - nmax0);
            float p1 = __expf(cS[nb][1] - nmax0);
            float p2 = __expf(cS[nb][2] - nmax1);
            float p3 = __expf(cS[nb][3] - nmax1);
            psum0 += p0 + p1;
            psum1 += p2 + p3;
            // write P as bf16x2 pairs (cols 2tig,2tig+1 -> word nb*4+tig)
            Pp[qrow * 36 + nb * 4 + tig]       = packbf(p0, p1);
            Pp[(qrow + 8) * 36 + nb * 4 + tig] = packbf(p2, p3);
        }
        psum0 += __shfl_xor_sync(0xffffffffu, psum0, 1);
        psum0 += __shfl_xor_sync(0xffffffffu, psum0, 2);
        psum1 += __shfl_xor_sync(0xffffffffu, psum1, 1);
        psum1 += __shfl_xor_sync(0xffffffffu, psum1, 2);
        rsum0 = rsum0 * f0 + psum0;
        rsum1 = rsum1 * f1 + psum1;

#pragma unroll
        for (int nb = 0; nb < 6; nb++) {
            o[nb][0] *= f0; o[nb][1] *= f0;
            o[nb][2] *= f1; o[nb][3] *= f1;
        }
        __syncwarp();   // P rows for this warp's PV are warp-local

        // ---- PV: O += P x V (bf16 m16n8k16, 4 k-chunks of 16 keys) ----
#pragma unroll
        for (int kb = 0; kb < 4; kb++) {
            uint32_t a0 = Pp[qrow * 36 + kb * 8 + tig];
            uint32_t a1 = Pp[(qrow + 8) * 36 + kb * 8 + tig];
            uint32_t a2 = Pp[qrow * 36 + kb * 8 + tig + 4];
            uint32_t a3 = Pp[(qrow + 8) * 36 + kb * 8 + tig + 4];
#pragma unroll
            for (int nb = 0; nb < 6; nb++) {
                uint32_t b0 = Vp[(nb * 8 + gid) * 36 + kb * 8 + tig];
                uint32_t b1 = Vp[(nb * 8 + gid) * 36 + kb * 8 + tig + 4];
                mma_bf16(o[nb], a0, a1, a2, a3, b0, b1);
            }
        }
    }

    const int mA = m0 + qrow;
    const int mB = mA + 8;
    float* op = g_opart + (split * BB + b) * CC * NN;
#pragma unroll
    for (int nb = 0; nb < 6; nb++) {
        int ch = nb * 8 + 2 * tig;
        op[ch * NN + mA]       = o[nb][0];
        op[(ch + 1) * NN + mA] = o[nb][1];
        op[ch * NN + mB]       = o[nb][2];
        op[(ch + 1) * NN + mB] = o[nb][3];
    }
    if (tig == 0) {
        g_mpart[(split * BB + b) * NN + mA] = rmax0;
        g_mpart[(split * BB + b) * NN + mB] = rmax1;
        g_lpart[(split * BB + b) * NN + mA] = rsum0;
        g_lpart[(split * BB + b) * NN + mB] = rsum1;
    }
}

// ---------------- window attention: 4 windows per 256-thread block --------------
__global__ void __launch_bounds__(256, 4) winattn_kernel() {
    int b  = blockIdx.z;
    int sp = blockIdx.y;
    int wg = threadIdx.x >> 6;
    int w  = blockIdx.x * 4 + wg;
    int t  = threadIdx.x & 63;

    __shared__ float qsm[4][64][17];
    __shared__ float vsm[4][64][17];

    int py, px;
    if (sp == 0)      { int wy = w >> 3, wx = w & 7; py = wy * 8 + (t >> 3); px = wx * 8 + (t & 7); }
    else if (sp == 1) { py = t;  px = w; }
    else              { py = w;  px = t; }
    int pix = py * 64 + px;

    int qbase = (b * 96 + sp * 32) * NN + pix;
#pragma unroll
    for (int c = 0; c < 16; c++) {
        qsm[wg][t][c] = g_x2[qbase + c * NN];
        vsm[wg][t][c] = g_x2[qbase + (16 + c) * NN];
    }
    __syncthreads();

    float qr[16];
#pragma unroll
    for (int c = 0; c < 16; c++) qr[c] = qsm[wg][t][c];

    float lg[64];
    float mx = -1e30f;
    for (int j = 0; j < 64; j++) {
        float d = 0.f;
#pragma unroll
        for (int c = 0; c < 16; c++) d += qr[c] * qsm[wg][j][c];
        lg[j] = d;
        mx = fmaxf(mx, d);
    }
    float s = 0.f;
    for (int j = 0; j < 64; j++) { lg[j] = __expf(lg[j] - mx); s += lg[j]; }
    float inv = 1.f / s;

    float o[16];
#pragma unroll
    for (int c = 0; c < 16; c++) o[c] = 0.f;
    for (int j = 0; j < 64; j++) {
        float p = lg[j] * inv;
#pragma unroll
        for (int c = 0; c < 16; c++) o[c] += p * vsm[wg][j][c];
    }
#pragma unroll
    for (int c = 0; c < 16; c++)
        g_win[(b * CC + sp * 16 + c) * NN + pix] = o[c];
}

// ---------------- final: MMA pout conv + split merge + average -------------------
__global__ void __launch_bounds__(256, 2) final_kernel(
    const float* __restrict__ pw, const float* __restrict__ pb,
    float* __restrict__ out) {
    __shared__ ConvSmem S;
    const int tid = threadIdx.x;
    const int b   = blockIdx.y;
    const int m0  = blockIdx.x * 128;

    if (tid < 48) { S.sc_s[tid] = 1.f; S.bias_s[tid] = pb[tid]; }
    __syncthreads();
    conv_fill(S, g_win + b * CC * NN, m0, pw, tid);
    __syncthreads();

    const int warp = tid >> 5, lane = tid & 31;
    const int gid = lane >> 2, tig = lane & 3;
    const int qrow = warp * 16 + gid;
    float cS[6][4];
    conv_mma(S, cS, qrow, tig, gid);

    const int mA = m0 + qrow;
    const int mB = mA + 8;

    float eA[NSPLIT], eB[NSPLIT];
    {
        float MA = -1e30f, MB = -1e30f;
        float mvA[NSPLIT], mvB[NSPLIT];
#pragma unroll
        for (int s = 0; s < NSPLIT; s++) {
            mvA[s] = g_mpart[(s * BB + b) * NN + mA];
            mvB[s] = g_mpart[(s * BB + b) * NN + mB];
            MA = fmaxf(MA, mvA[s]); MB = fmaxf(MB, mvB[s]);
        }
        float lA = 0.f, lB = 0.f;
#pragma unroll
        for (int s = 0; s < NSPLIT; s++) {
            eA[s] = __expf(mvA[s] - MA);
            eB[s] = __expf(mvB[s] - MB);
            lA += g_lpart[(s * BB + b) * NN + mA] * eA[s];
            lB += g_lpart[(s * BB + b) * NN + mB] * eB[s];
        }
        float ilA = 0.5f / lA, ilB = 0.5f / lB;
#pragma unroll
        for (int s = 0; s < NSPLIT; s++) { eA[s] *= ilA; eB[s] *= ilB; }
    }

#pragma unroll
    for (int nb = 0; nb < 6; nb++) {
        int col = nb * 8 + 2 * tig;
#pragma unroll
        for (int j = 0; j < 2; j++) {
            int ch = col + j;
            float odA = 0.f, odB = 0.f;
#pragma unroll
            for (int s = 0; s < NSPLIT; s++) {
                odA += g_opart[((s * BB + b) * CC + ch) * NN + mA] * eA[s];
                odB += g_opart[((s * BB + b) * CC + ch) * NN + mB] * eB[s];
            }
            out[(b * CC + ch) * NN + mA] = 0.5f * cS[nb][j]     + odA;
            out[(b * CC + ch) * NN + mB] = 0.5f * cS[nb][2 + j] + odB;
        }
    }
}

// ---------------- launch ---------------------------------------------------------
extern "C" void kernel_launch(void* const* d_in, const int* in_sizes, int n_in,
                              void* d_out, int out_size) {
    const float* x        = (const float*)d_in[0];
    const float* Wq       = (const float*)d_in[1];
    const float* bq       = (const float*)d_in[2];
    const float* off_dw_w = (const float*)d_in[3];
    const float* off_dw_b = (const float*)d_in[4];
    const float* off_ln_g = (const float*)d_in[5];
    const float* off_ln_b = (const float*)d_in[6];
    const float* off_pw_w = (const float*)d_in[7];
    const float* Wk       = (const float*)d_in[8];
    const float* bk       = (const float*)d_in[9];
    const float* Wv       = (const float*)d_in[10];
    const float* bv       = (const float*)d_in[11];
    const float* inp_w    = (const float*)d_in[12];
    const float* inp_b    = (const float*)d_in[13];
    const float* bn_g     = (const float*)d_in[14];
    const float* bn_b     = (const float*)d_in[15];
    const float* bn_mean  = (const float*)d_in[16];
    const float* bn_var   = (const float*)d_in[17];
    const float* pout_w   = (const float*)d_in[18];
    const float* pout_b   = (const float*)d_in[19];
    const float* rpe      = (const float*)d_in[20];
    float* out = (float*)d_out;

    cudaFuncSetAttribute(attn_kernel, cudaFuncAttributeMaxDynamicSharedMemorySize,
                         ATTN_SMEM_BYTES);

    stage1_kernel<<<dim3(32, 7), 256>>>(x, Wq, bq, inp_w, inp_b,
                                        bn_g, bn_b, bn_mean, bn_var, rpe);
    deform_kernel<<<dim3(HH, BB), 512>>>(x, off_dw_w, off_dw_b,
                                         off_ln_g, off_ln_b, off_pw_w);
    stage2_kernel<<<dim3(32, 4), 256>>>(Wk, bk, Wv, bv);
    attn_kernel<<<dim3(NN / 128, NSPLIT, BB), 256, ATTN_SMEM_BYTES>>>();
    winattn_kernel<<<dim3(16, 3, BB), 256>>>();
    final_kernel<<<dim3(32, BB), 256>>>(pout_w, pout_b, out);
}